// round 1
// baseline (speedup 1.0000x reference)
#include <cuda_runtime.h>

// Problem constants
#define B_ 4
#define D_ 64
#define K_ 32
#define N_ 8192               // T*H*W = 8*32*32
#define THREADS 256
#define ITEMS 8
#define CHUNK (THREADS*ITEMS) // 2048 voxels per block
#define CHUNKS (N_/CHUNK)     // 4 blocks per (b,d)

// Scratch (no allocations allowed)
__device__ float g_partial[B_*D_*CHUNKS]; // per-block partial sums of E over n
__device__ float g_gamma[B_*D_];

__device__ __forceinline__ float ex2(float x) {
    float y;
    asm("ex2.approx.f32 %0, %1;" : "=f"(y) : "f"(x));
    return y;
}

// Kernel 1: compute E[b,d,n] = sum_k softmax_k(scale*r^2) * r, write to out,
// and per-block partial sums of E (deterministic reduction, no atomics).
__global__ void __launch_bounds__(THREADS)
k_main(const float* __restrict__ X, const float* __restrict__ cw,
       const float* __restrict__ sc, float* __restrict__ out)
{
    __shared__ float s_c[K_];
    __shared__ float s_sl[K_];
    __shared__ float s_red[THREADS/32];

    const int bd    = blockIdx.x / CHUNKS;   // b*64 + d
    const int chunk = blockIdx.x % CHUNKS;
    const int d     = bd & (D_-1);
    const int t     = threadIdx.x;

    if (t < K_) {
        s_c[t]  = cw[t*D_ + d];
        // fold log2(e) so the exp is a single MUFU.EX2
        s_sl[t] = sc[t*D_ + d] * 1.4426950408889634f;
    }
    __syncthreads();

    const float* xp = X + (size_t)bd * N_ + chunk * CHUNK;

    float x[ITEMS], num[ITEMS], den[ITEMS];
    float4 v0 = reinterpret_cast<const float4*>(xp)[t];
    float4 v1 = reinterpret_cast<const float4*>(xp)[t + THREADS];
    x[0]=v0.x; x[1]=v0.y; x[2]=v0.z; x[3]=v0.w;
    x[4]=v1.x; x[5]=v1.y; x[6]=v1.z; x[7]=v1.w;
    #pragma unroll
    for (int i = 0; i < ITEMS; i++) { num[i] = 0.f; den[i] = 0.f; }

    #pragma unroll 8
    for (int k = 0; k < K_; k++) {
        const float c  = s_c[k];
        const float sl = s_sl[k];
        #pragma unroll
        for (int i = 0; i < ITEMS; i++) {
            float r = x[i] - c;
            float e = ex2(sl * r * r);   // exp(scale*r^2); arg <= 0, no overflow
            den[i] += e;
            num[i]  = fmaf(e, r, num[i]);
        }
    }

    float E[ITEMS];
    float sum = 0.f;
    #pragma unroll
    for (int i = 0; i < ITEMS; i++) {
        E[i] = __fdividef(num[i], den[i]);
        sum += E[i];
    }

    float* op = out + (size_t)bd * N_ + chunk * CHUNK;
    reinterpret_cast<float4*>(op)[t]           = make_float4(E[0],E[1],E[2],E[3]);
    reinterpret_cast<float4*>(op)[t + THREADS] = make_float4(E[4],E[5],E[6],E[7]);

    // block-deterministic reduction of sum(E) over this chunk
    #pragma unroll
    for (int o = 16; o > 0; o >>= 1)
        sum += __shfl_xor_sync(0xffffffffu, sum, o);
    if ((t & 31) == 0) s_red[t >> 5] = sum;
    __syncthreads();
    if (t == 0) {
        float s = 0.f;
        #pragma unroll
        for (int w = 0; w < THREADS/32; w++) s += s_red[w];
        g_partial[blockIdx.x] = s;   // blockIdx.x == bd*CHUNKS + chunk
    }
}

// Kernel 2: gamma[b,i] = sigmoid( sum_j Eglob[b,j]*fc_w[i,j] + fc_b[i] ),
// Eglob[b,j] = (1/K) * sum over partials. One block, 256 threads.
__global__ void __launch_bounds__(256)
k_gamma(const float* __restrict__ fw, const float* __restrict__ fb)
{
    __shared__ float s_e[B_*D_];
    const int t = threadIdx.x;   // 0..255 -> (b,j)
    float s = 0.f;
    #pragma unroll
    for (int c = 0; c < CHUNKS; c++) s += g_partial[t*CHUNKS + c];
    s_e[t] = s * (1.0f / K_);
    __syncthreads();

    const int b = t >> 6;
    const int i = t & 63;
    float acc = fb[i];
    #pragma unroll
    for (int j = 0; j < D_; j++)
        acc = fmaf(s_e[b*D_ + j], fw[i*D_ + j], acc);
    g_gamma[t] = 1.f / (1.f + __expf(-acc));
}

// Kernel 3: out = relu(E * (1 + gamma[b,d])), in place on out.
__global__ void __launch_bounds__(256)
k_scale(float* __restrict__ out)
{
    const int idx = blockIdx.x * blockDim.x + threadIdx.x;  // float4 index
    const int bd  = idx / (N_/4);
    const float g = 1.f + g_gamma[bd];
    float4 v = reinterpret_cast<float4*>(out)[idx];
    v.x = fmaxf(v.x * g, 0.f);
    v.y = fmaxf(v.y * g, 0.f);
    v.z = fmaxf(v.z * g, 0.f);
    v.w = fmaxf(v.w * g, 0.f);
    reinterpret_cast<float4*>(out)[idx] = v;
}

extern "C" void kernel_launch(void* const* d_in, const int* in_sizes, int n_in,
                              void* d_out, int out_size)
{
    const float* X   = (const float*)d_in[0];  // (B,D,T,H,W)
    const float* cw  = (const float*)d_in[1];  // (K,D)
    const float* sc  = (const float*)d_in[2];  // (K,D)
    const float* fcw = (const float*)d_in[3];  // (D,D)
    const float* fcb = (const float*)d_in[4];  // (D,)
    float* out = (float*)d_out;

    k_main<<<B_*D_*CHUNKS, THREADS>>>(X, cw, sc, out);
    k_gamma<<<1, 256>>>(fcw, fcb);
    const int n4 = (B_*D_*N_) / 4;
    k_scale<<<n4 / 256, 256>>>(out);
}

// round 2
// speedup vs baseline: 1.0577x; 1.0577x over previous
#include <cuda_runtime.h>

// Problem: B=4, D=64, K=32, N=8192 (8*32*32). Total floats = 2,097,152.
#define Bk 4
#define Dk 64
#define Kk 32
#define Nk 8192
#define GRID 512
#define TPB 256
#define F4_PER_SLICE 131072   // one batch = 524288 floats = 131072 float4

typedef unsigned long long u64;

// Scratch (no allocations allowed). g_count self-resets to 0 every launch.
__device__ unsigned g_count = 0;
__device__ float g_partial[4 * GRID];   // [slice(=b)][blk]

__device__ __forceinline__ float ex2(float x) {
    float y; asm("ex2.approx.f32 %0, %1;" : "=f"(y) : "f"(x)); return y;
}
__device__ __forceinline__ u64 pk(float lo, float hi) {
    u64 r; asm("mov.b64 %0, {%1,%2};" : "=l"(r) : "f"(lo), "f"(hi)); return r;
}
__device__ __forceinline__ void upk(float& lo, float& hi, u64 v) {
    asm("mov.b64 {%0,%1}, %2;" : "=f"(lo), "=f"(hi) : "l"(v));
}
__device__ __forceinline__ u64 add2(u64 a, u64 b) {
    u64 r; asm("add.rn.f32x2 %0, %1, %2;" : "=l"(r) : "l"(a), "l"(b)); return r;
}
__device__ __forceinline__ u64 mul2(u64 a, u64 b) {
    u64 r; asm("mul.rn.f32x2 %0, %1, %2;" : "=l"(r) : "l"(a), "l"(b)); return r;
}
__device__ __forceinline__ u64 fma2(u64 a, u64 b, u64 c) {
    u64 r; asm("fma.rn.f32x2 %0, %1, %2, %3;" : "=l"(r) : "l"(a), "l"(b), "l"(c)); return r;
}

__global__ void __launch_bounds__(TPB, 4)
k_fused(const float* __restrict__ X, const float* __restrict__ cw,
        const float* __restrict__ sc, const float* __restrict__ fw,
        const float* __restrict__ fb, float* __restrict__ out)
{
    __shared__ float s_c[Kk];
    __shared__ float s_sl[Kk];
    __shared__ float s_fw[Dk];
    __shared__ float s_fb;
    __shared__ float s_wred[TPB / 32][4];
    __shared__ float s_eg[Bk * Dk];
    __shared__ float s_gamma[Bk];

    const int t   = threadIdx.x;
    const int blk = blockIdx.x;
    const int d   = blk >> 3;           // all threads of a block share one d
    const unsigned tid = blk * TPB + t; // float4 index within a slice

    if (t < Kk) {
        s_c[t]  = cw[t * Dk + d];
        s_sl[t] = sc[t * Dk + d] * 1.4426950408889634f;  // fold log2(e)
    }
    if (t < Dk) s_fw[t] = fw[d * Dk + t];  // fc_w row d (prefetched pre-barrier)
    if (t == 0) s_fb = fb[d];
    __syncthreads();

    const float4* X4 = (const float4*)X;
    float4*       O4 = (float4*)out;

    u64  E[8];      // E pairs: slice s -> E[2s], E[2s+1]  (kept in regs across barrier)
    float ssum[4];  // per-slice sum of E for this thread

    // ---- Phase 1: E = sum_k softmax_k(scale*r^2)*r, packed f32x2, 2 groups of 2 slices ----
    #pragma unroll
    for (int grp = 0; grp < 2; grp++) {
        u64 x2[4], num[4], den[4];
        #pragma unroll
        for (int h = 0; h < 2; h++) {
            int s = grp * 2 + h;
            float4 v = X4[tid + s * F4_PER_SLICE];
            x2[h * 2 + 0] = pk(v.x, v.y);
            x2[h * 2 + 1] = pk(v.z, v.w);
        }
        #pragma unroll
        for (int p = 0; p < 4; p++) { num[p] = 0ull; den[p] = 0ull; }

        #pragma unroll 4
        for (int k = 0; k < Kk; k++) {
            const float c  = s_c[k];
            const float sl = s_sl[k];
            const u64 nc2  = pk(-c, -c);
            const u64 sl22 = pk(sl, sl);
            #pragma unroll
            for (int p = 0; p < 4; p++) {
                u64 r = add2(x2[p], nc2);       // r = x - c
                u64 a = mul2(r, r);             // r^2
                a = mul2(a, sl22);              // sl*log2e * r^2  (<= 0)
                float alo, ahi; upk(alo, ahi, a);
                u64 e = pk(ex2(alo), ex2(ahi)); // exp(scale*r^2)
                den[p] = add2(den[p], e);
                num[p] = fma2(e, r, num[p]);
            }
        }

        #pragma unroll
        for (int h = 0; h < 2; h++) {
            float n0, n1, n2, n3, d0, d1, d2, d3;
            upk(n0, n1, num[h * 2]); upk(n2, n3, num[h * 2 + 1]);
            upk(d0, d1, den[h * 2]); upk(d2, d3, den[h * 2 + 1]);
            float e0 = __fdividef(n0, d0), e1 = __fdividef(n1, d1);
            float e2 = __fdividef(n2, d2), e3 = __fdividef(n3, d3);
            E[(grp * 2 + h) * 2 + 0] = pk(e0, e1);
            E[(grp * 2 + h) * 2 + 1] = pk(e2, e3);
            ssum[grp * 2 + h] = (e0 + e1) + (e2 + e3);
        }
    }

    // ---- Block reduction of per-slice E sums -> deterministic partials ----
    #pragma unroll
    for (int s = 0; s < 4; s++) {
        float v = ssum[s];
        #pragma unroll
        for (int o = 16; o > 0; o >>= 1) v += __shfl_xor_sync(0xffffffffu, v, o);
        if ((t & 31) == 0) s_wred[t >> 5][s] = v;
    }
    __syncthreads();
    if (t < 4) {
        float acc = 0.f;
        #pragma unroll
        for (int w = 0; w < TPB / 32; w++) acc += s_wred[w][t];
        g_partial[t * GRID + blk] = acc;
        __threadfence();
    }
    __syncthreads();

    // ---- Grid barrier (self-resetting, graph-replayable) ----
    if (t == 0) {
        atomicAdd(&g_count, 1u);
        while (*(volatile unsigned*)&g_count < (unsigned)GRID) __nanosleep(32);
        unsigned p2 = atomicAdd(&g_count, 1u);
        if (p2 == 2u * GRID - 1u) g_count = 0;   // last block resets for next replay
    }
    __syncthreads();
    __threadfence();

    // ---- Phase 2: E_glob and gamma (redundantly per block, tiny) ----
    {
        const int b = t >> 6, j = t & 63;
        const float* gp = &g_partial[b * GRID + j * 8];
        float s = 0.f;
        #pragma unroll
        for (int r = 0; r < 8; r++) s += __ldcg(gp + r);
        s_eg[t] = s * (1.0f / Kk);
    }
    __syncthreads();
    if (t < 4) {
        float acc = s_fb;
        #pragma unroll
        for (int j = 0; j < Dk; j++) acc = fmaf(s_eg[t * Dk + j], s_fw[j], acc);
        s_gamma[t] = 1.f + 1.f / (1.f + __expf(-acc));   // 1 + sigmoid
    }
    __syncthreads();

    // ---- Phase 3: scale registers, single write of output ----
    #pragma unroll
    for (int s = 0; s < 4; s++) {
        const float g = s_gamma[s];
        float e0, e1, e2, e3;
        upk(e0, e1, E[s * 2]); upk(e2, e3, E[s * 2 + 1]);
        float4 o;
        o.x = fmaxf(e0 * g, 0.f);
        o.y = fmaxf(e1 * g, 0.f);
        o.z = fmaxf(e2 * g, 0.f);
        o.w = fmaxf(e3 * g, 0.f);
        O4[tid + s * F4_PER_SLICE] = o;
    }
}

extern "C" void kernel_launch(void* const* d_in, const int* in_sizes, int n_in,
                              void* d_out, int out_size)
{
    const float* X   = (const float*)d_in[0];  // (B,D,T,H,W)
    const float* cw  = (const float*)d_in[1];  // (K,D)
    const float* sc  = (const float*)d_in[2];  // (K,D)
    const float* fcw = (const float*)d_in[3];  // (D,D)
    const float* fcb = (const float*)d_in[4];  // (D,)
    float* out = (float*)d_out;

    k_fused<<<GRID, TPB>>>(X, cw, sc, fcw, fcb, out);
}

// round 3
// speedup vs baseline: 1.0624x; 1.0045x over previous
#include <cuda_runtime.h>

// Problem: B=4, D=64, K=32, N=8192 (8*32*32). Total floats = 2,097,152.
#define Bk 4
#define Dk 64
#define Kk 32
#define GRID 512
#define TPB 256
#define F4_PER_SLICE 131072   // one batch = 524288 floats = 131072 float4

typedef unsigned long long u64;

// Scratch (no allocations allowed). g_count self-resets to 0 every launch.
__device__ unsigned g_count = 0;
__device__ float g_partial[Bk * GRID];   // [slice(=b)][blk]

__device__ __forceinline__ float ex2(float x) {
    float y; asm("ex2.approx.f32 %0, %1;" : "=f"(y) : "f"(x)); return y;
}
__device__ __forceinline__ u64 pk(float lo, float hi) {
    u64 r; asm("mov.b64 %0, {%1,%2};" : "=l"(r) : "f"(lo), "f"(hi)); return r;
}
__device__ __forceinline__ void upk(float& lo, float& hi, u64 v) {
    asm("mov.b64 {%0,%1}, %2;" : "=f"(lo), "=f"(hi) : "l"(v));
}
__device__ __forceinline__ u64 add2(u64 a, u64 b) {
    u64 r; asm("add.rn.f32x2 %0, %1, %2;" : "=l"(r) : "l"(a), "l"(b)); return r;
}
__device__ __forceinline__ u64 mul2(u64 a, u64 b) {
    u64 r; asm("mul.rn.f32x2 %0, %1, %2;" : "=l"(r) : "l"(a), "l"(b)); return r;
}
__device__ __forceinline__ u64 fma2(u64 a, u64 b, u64 c) {
    u64 r; asm("fma.rn.f32x2 %0, %1, %2, %3;" : "=l"(r) : "l"(a), "l"(b), "l"(c)); return r;
}

__global__ void __launch_bounds__(TPB, 4)
k_fused(const float* __restrict__ X, const float* __restrict__ cw,
        const float* __restrict__ sc, const float* __restrict__ fw,
        const float* __restrict__ fb, float* __restrict__ out)
{
    // per-k packed constants (duplicated lanes) for the expanded exponent:
    //   arg = slx*x^2 + p1*x + p0,  slx = scale*log2(e), p1 = -2c*slx, p0 = c^2*slx
    __shared__ u64 s_p1[Kk], s_p0[Kk], s_sl[Kk], s_nc[Kk];
    __shared__ float s_fw[Dk];
    __shared__ float s_fb;
    __shared__ float s_wred[TPB / 32][Bk];
    __shared__ float s_eg[Bk * Dk];
    __shared__ float s_gamma[Bk];

    const int t   = threadIdx.x;
    const int blk = blockIdx.x;
    const int d   = blk >> 3;           // all threads of a block share one d
    const unsigned tid = blk * TPB + t; // float4 index within a slice

    if (t < Kk) {
        const float c   = cw[t * Dk + d];
        const float slx = sc[t * Dk + d] * 1.4426950408889634f;
        const float p1  = -2.0f * c * slx;
        const float p0  = c * c * slx;
        s_p1[t] = pk(p1, p1);
        s_p0[t] = pk(p0, p0);
        s_sl[t] = pk(slx, slx);
        s_nc[t] = pk(-c, -c);
    }
    if (t < Dk) s_fw[t] = fw[d * Dk + t];  // fc_w row d (prefetched pre-barrier)
    if (t == 0) s_fb = fb[d];
    __syncthreads();

    const float4* X4 = (const float4*)X;
    float4*       O4 = (float4*)out;

    u64   Eacc[8];   // E pairs kept in regs across the grid barrier
    float ssum[Bk];  // per-slice sum of E for this thread

    // ---- Phase 1: two groups of 2 slices; 4 element-pairs per group ----
    #pragma unroll
    for (int grp = 0; grp < 2; grp++) {
        u64 x2[4], xx2[4], den2[4], w2[4];
        #pragma unroll
        for (int h = 0; h < 2; h++) {
            const int s = grp * 2 + h;
            float4 v = X4[tid + s * F4_PER_SLICE];
            x2[h * 2 + 0] = pk(v.x, v.y);
            x2[h * 2 + 1] = pk(v.z, v.w);
        }
        #pragma unroll
        for (int p = 0; p < 4; p++) {
            xx2[p]  = mul2(x2[p], x2[p]);
            den2[p] = 0ull;
            w2[p]   = 0ull;
        }

        #pragma unroll 8
        for (int k = 0; k < Kk; k++) {
            const u64 p1 = s_p1[k], p0 = s_p0[k], sl = s_sl[k], nc = s_nc[k];
            #pragma unroll
            for (int p = 0; p < 4; p++) {
                u64 a = fma2(p1, x2[p], p0);
                a = fma2(sl, xx2[p], a);          // arg = slx*x^2 + p1*x + p0  (<= 0)
                float alo, ahi; upk(alo, ahi, a);
                u64 e = pk(ex2(alo), ex2(ahi));   // exp(scale*r^2), pair-aliased regs
                den2[p] = add2(den2[p], e);
                w2[p]   = fma2(e, nc, w2[p]);     // w = sum e*(-c)
            }
        }

        #pragma unroll
        for (int p = 0; p < 4; p++) {
            u64 num = fma2(x2[p], den2[p], w2[p]);  // num = x*den - sum(e*c)
            float n0, n1, d0, d1;
            upk(n0, n1, num);
            upk(d0, d1, den2[p]);
            const float e0 = __fdividef(n0, d0);
            const float e1 = __fdividef(n1, d1);
            Eacc[grp * 4 + p] = pk(e0, e1);
            const int s = grp * 2 + (p >> 1);
            if ((p & 1) == 0) ssum[s] = e0 + e1; else ssum[s] += e0 + e1;
        }
    }

    // ---- Block reduction of per-slice E sums -> deterministic partials ----
    #pragma unroll
    for (int s = 0; s < Bk; s++) {
        float v = ssum[s];
        #pragma unroll
        for (int o = 16; o > 0; o >>= 1) v += __shfl_xor_sync(0xffffffffu, v, o);
        if ((t & 31) == 0) s_wred[t >> 5][s] = v;
    }
    __syncthreads();
    if (t < Bk) {
        float acc = 0.f;
        #pragma unroll
        for (int w = 0; w < TPB / 32; w++) acc += s_wred[w][t];
        g_partial[t * GRID + blk] = acc;
        __threadfence();
    }
    __syncthreads();

    // ---- Grid barrier (self-resetting, graph-replayable) ----
    if (t == 0) {
        atomicAdd(&g_count, 1u);
        while (*(volatile unsigned*)&g_count < (unsigned)GRID) __nanosleep(32);
        unsigned p2 = atomicAdd(&g_count, 1u);
        if (p2 == 2u * GRID - 1u) g_count = 0;   // last block resets for next replay
    }
    __syncthreads();
    __threadfence();

    // ---- Phase 2: E_glob and gamma (redundantly per block, tiny) ----
    {
        const int b = t >> 6, j = t & 63;
        const float* gp = &g_partial[b * GRID + j * 8];
        float s = 0.f;
        #pragma unroll
        for (int r = 0; r < 8; r++) s += __ldcg(gp + r);
        s_eg[t] = s * (1.0f / Kk);
    }
    __syncthreads();
    if (t < Bk) {
        float acc = s_fb;
        #pragma unroll
        for (int j = 0; j < Dk; j++) acc = fmaf(s_eg[t * Dk + j], s_fw[j], acc);
        s_gamma[t] = 1.f + 1.f / (1.f + __expf(-acc));   // 1 + sigmoid
    }
    __syncthreads();

    // ---- Phase 3: scale registers, single write of output ----
    #pragma unroll
    for (int s = 0; s < Bk; s++) {
        const float g = s_gamma[s];
        const u64 g2 = pk(g, g);
        u64 a = mul2(Eacc[s * 2 + 0], g2);
        u64 b = mul2(Eacc[s * 2 + 1], g2);
        float4 o;
        upk(o.x, o.y, a);
        upk(o.z, o.w, b);
        o.x = fmaxf(o.x, 0.f); o.y = fmaxf(o.y, 0.f);
        o.z = fmaxf(o.z, 0.f); o.w = fmaxf(o.w, 0.f);
        O4[tid + s * F4_PER_SLICE] = o;
    }
}

extern "C" void kernel_launch(void* const* d_in, const int* in_sizes, int n_in,
                              void* d_out, int out_size)
{
    const float* X   = (const float*)d_in[0];  // (B,D,T,H,W)
    const float* cw  = (const float*)d_in[1];  // (K,D)
    const float* sc  = (const float*)d_in[2];  // (K,D)
    const float* fcw = (const float*)d_in[3];  // (D,D)
    const float* fcb = (const float*)d_in[4];  // (D,)
    float* out = (float*)d_out;

    k_fused<<<GRID, TPB>>>(X, cw, sc, fcw, fcb, out);
}